// round 15
// baseline (speedup 1.0000x reference)
#include <cuda_runtime.h>
#include <cuda_bf16.h>
#include <cuda_fp16.h>
#include <cstdint>

#define VOCAB 32000
#define EDIM  128
#define HDIM  256
#define NBATCH 8
#define SEQ   512
#define MTOT  (NBATCH * SEQ)   // 4096
#define G3    (3 * HDIM)       // 768

// ---- scratch (static device globals; no allocation) ----
__device__ float g_gi[MTOT * G3];
__device__ __half g_A2[(size_t)MTOT * HDIM];    // [4096][256] fp16 hidden
__device__ __half g_B2[(size_t)VOCAB * HDIM];   // [32000][256] fp16 w_out

// ---- packed f32x2 helpers ----
__device__ __forceinline__ unsigned long long f2_pack(float x, float y) {
    unsigned long long r;
    asm("mov.b64 %0, {%1, %2};" : "=l"(r) : "f"(x), "f"(y));
    return r;
}
__device__ __forceinline__ unsigned long long f2_fma(unsigned long long a,
                                                     unsigned long long b,
                                                     unsigned long long c) {
    unsigned long long d;
    asm("fma.rn.f32x2 %0, %1, %2, %3;" : "=l"(d) : "l"(a), "l"(b), "l"(c));
    return d;
}
__device__ __forceinline__ unsigned long long f2_add(unsigned long long a,
                                                     unsigned long long b) {
    unsigned long long d;
    asm("add.rn.f32x2 %0, %1, %2;" : "=l"(d) : "l"(a), "l"(b));
    return d;
}
__device__ __forceinline__ void f2_unpack(unsigned long long v, float& lo, float& hi) {
    asm("mov.b64 {%0, %1}, %2;" : "=f"(lo), "=f"(hi) : "l"(v));
}
__device__ __forceinline__ uint32_t smem_u32(const void* p) {
    uint32_t a;
    asm("{ .reg .u64 t; cvta.to.shared.u64 t, %1; cvt.u32.u64 %0, t; }"
        : "=r"(a) : "l"(p));
    return a;
}

// ---- cluster / DSMEM helpers (sm_90 baseline PTX, no 'a' gating) ----
__device__ __forceinline__ uint32_t mapa_u32(uint32_t saddr, uint32_t rank) {
    uint32_t r;
    asm("mapa.shared::cluster.u32 %0, %1, %2;" : "=r"(r) : "r"(saddr), "r"(rank));
    return r;
}
__device__ __forceinline__ void st_clu64(uint32_t addr, unsigned long long v) {
    asm volatile("st.relaxed.cluster.shared::cluster.b64 [%0], %1;"
                 :: "r"(addr), "l"(v) : "memory");
}
__device__ __forceinline__ unsigned long long ld_clu64(uint32_t addr) {
    unsigned long long v;
    asm volatile("ld.relaxed.cluster.shared::cluster.b64 %0, [%1];"
                 : "=l"(v) : "r"(addr) : "memory");
    return v;
}
#define CLUSTER_BAR() do {                                          \
    asm volatile("barrier.cluster.arrive.aligned;" ::: "memory");   \
    asm volatile("barrier.cluster.wait.aligned;" ::: "memory");     \
} while (0)

// ---- mma.sync / ldmatrix / cp.async helpers (sm_80+ PTX, target-safe) ----
__device__ __forceinline__ void ldsm4(uint32_t addr, uint32_t& r0, uint32_t& r1,
                                      uint32_t& r2, uint32_t& r3) {
    asm volatile("ldmatrix.sync.aligned.m8n8.x4.shared.b16 {%0,%1,%2,%3}, [%4];"
                 : "=r"(r0), "=r"(r1), "=r"(r2), "=r"(r3) : "r"(addr));
}
__device__ __forceinline__ void mma16816h(float* c, uint32_t a0, uint32_t a1,
                                          uint32_t a2, uint32_t a3,
                                          uint32_t b0, uint32_t b1) {
    asm volatile(
        "mma.sync.aligned.m16n8k16.row.col.f32.f16.f16.f32 "
        "{%0,%1,%2,%3}, {%4,%5,%6,%7}, {%8,%9}, {%0,%1,%2,%3};"
        : "+f"(c[0]), "+f"(c[1]), "+f"(c[2]), "+f"(c[3])
        : "r"(a0), "r"(a1), "r"(a2), "r"(a3), "r"(b0), "r"(b1));
}
__device__ __forceinline__ void cpa16(uint32_t s, const void* g) {
    asm volatile("cp.async.cg.shared.global [%0], [%1], 16;" :: "r"(s), "l"(g));
}
#define CPA_COMMIT() asm volatile("cp.async.commit_group;" ::: "memory")
#define CPA_WAIT0()  asm volatile("cp.async.wait_group 0;" ::: "memory")

// =====================================================================
// Kernel A v2: gi = emb[t] @ w_ih^T + b_ih  (verified R14 version).
// =====================================================================
#define E_ASTRIDE 260
#define E_BSTRIDE 132
#define E_NCH     8
#define EMB_SMEM  ((2 * 16 * E_ASTRIDE + 2 * 16 * E_BSTRIDE) * (int)sizeof(float))

__global__ void __launch_bounds__(256, 2)
embed_gi_kernel(const int* __restrict__ t,
                const float* __restrict__ emb,
                const float* __restrict__ w_ih,
                const float* __restrict__ b_ih) {
    extern __shared__ float esm[];
    float* As2 = esm;
    float* Bsm = esm + 2 * 16 * E_ASTRIDE;
    __shared__ int tok[128];

    int tid = threadIdx.x;
    int n0 = blockIdx.x * 128;
    int m0 = blockIdx.y * 128;

    if (tid < 128) tok[tid] = t[m0 + tid];
    __syncthreads();

    int lrow = tid >> 2;
    int lc4  = (tid & 3) * 4;

    const float* a0p = &emb[(size_t)tok[lrow] * EDIM + lc4];
    const float* a1p = &emb[(size_t)tok[lrow + 64] * EDIM + lc4];
    const float* b0p = &w_ih[(size_t)(n0 + lrow) * EDIM + lc4];
    const float* b1p = b0p + (size_t)64 * EDIM;

    auto stage = [&](int nb, float4 xa0, float4 xa1, float4 xb0, float4 xb1) {
        float* ab = &As2[nb * 16 * E_ASTRIDE];
        float* bb = &Bsm[nb * 16 * E_BSTRIDE];
        float av0[4] = {xa0.x, xa0.y, xa0.z, xa0.w};
        float av1[4] = {xa1.x, xa1.y, xa1.z, xa1.w};
        float bv0[4] = {xb0.x, xb0.y, xb0.z, xb0.w};
        float bv1[4] = {xb1.x, xb1.y, xb1.z, xb1.w};
#pragma unroll
        for (int c = 0; c < 4; c++) {
            *reinterpret_cast<unsigned long long*>(
                &ab[(lc4 + c) * E_ASTRIDE + 2 * lrow]) = f2_pack(av0[c], av0[c]);
            *reinterpret_cast<unsigned long long*>(
                &ab[(lc4 + c) * E_ASTRIDE + 2 * (lrow + 64)]) =
                f2_pack(av1[c], av1[c]);
            bb[(lc4 + c) * E_BSTRIDE + lrow]      = bv0[c];
            bb[(lc4 + c) * E_BSTRIDE + lrow + 64] = bv1[c];
        }
    };

    {
        float4 xa0 = *reinterpret_cast<const float4*>(a0p);
        float4 xa1 = *reinterpret_cast<const float4*>(a1p);
        float4 xb0 = *reinterpret_cast<const float4*>(b0p);
        float4 xb1 = *reinterpret_cast<const float4*>(b1p);
        stage(0, xa0, xa1, xb0, xb1);
    }
    __syncthreads();

    int tm = tid >> 4;
    int tn = tid & 15;

    unsigned long long c2[8][4];
#pragma unroll
    for (int i = 0; i < 8; i++)
#pragma unroll
        for (int j = 0; j < 4; j++) c2[i][j] = 0ull;

    for (int ksg = 0; ksg < E_NCH; ksg++) {
        int buf = ksg & 1;
        float4 na0, na1, nb0, nb1;
        if (ksg < E_NCH - 1) {
            int off = (ksg + 1) * 16;
            na0 = *reinterpret_cast<const float4*>(a0p + off);
            na1 = *reinterpret_cast<const float4*>(a1p + off);
            nb0 = *reinterpret_cast<const float4*>(b0p + off);
            nb1 = *reinterpret_cast<const float4*>(b1p + off);
        }
#pragma unroll
        for (int kk = 0; kk < 16; kk++) {
            const unsigned long long* arow =
                reinterpret_cast<const unsigned long long*>(
                    &As2[(buf * 16 + kk) * E_ASTRIDE]) + tm * 8;
            const float* brow = &Bsm[(buf * 16 + kk) * E_BSTRIDE + tn * 8];
            ulonglong2 bq0 = *reinterpret_cast<const ulonglong2*>(brow);
            ulonglong2 bq1 = *reinterpret_cast<const ulonglong2*>(brow + 4);
#pragma unroll
            for (int i = 0; i < 8; i++) {
                unsigned long long ap = arow[i];
                c2[i][0] = f2_fma(ap, bq0.x, c2[i][0]);
                c2[i][1] = f2_fma(ap, bq0.y, c2[i][1]);
                c2[i][2] = f2_fma(ap, bq1.x, c2[i][2]);
                c2[i][3] = f2_fma(ap, bq1.y, c2[i][3]);
            }
        }
        if (ksg < E_NCH - 1) {
            __syncthreads();
            stage(buf ^ 1, na0, na1, nb0, nb1);
            __syncthreads();
        }
    }

    float4 bb0 = *reinterpret_cast<const float4*>(&b_ih[n0 + tn * 8]);
    float4 bb1 = *reinterpret_cast<const float4*>(&b_ih[n0 + tn * 8 + 4]);
    unsigned long long bo[4] = {f2_pack(bb0.x, bb0.y), f2_pack(bb0.z, bb0.w),
                                f2_pack(bb1.x, bb1.y), f2_pack(bb1.z, bb1.w)};
#pragma unroll
    for (int i = 0; i < 8; i++) {
        union { unsigned long long u[4]; float4 f[2]; } r;
        r.u[0] = f2_add(c2[i][0], bo[0]);
        r.u[1] = f2_add(c2[i][1], bo[1]);
        r.u[2] = f2_add(c2[i][2], bo[2]);
        r.u[3] = f2_add(c2[i][3], bo[3]);
        float* orow = &g_gi[(size_t)(m0 + tm * 8 + i) * G3 + n0 + tn * 8];
        *reinterpret_cast<float4*>(orow)     = r.f[0];
        *reinterpret_cast<float4*>(orow + 4) = r.f[1];
    }
}

// =====================================================================
// Kernel B: GRU recurrence with DSMEM tag exchange (verified R9-R14)
// PLUS worker clusters (w_out -> fp16). Fast-math combine (R14).
// =====================================================================
#define GRU_NBLK 64
#define GRU_TPB  384
#define WRK_NBLK 56
#define TOT_NBLK (GRU_NBLK + WRK_NBLK)   // 120, divisible by 8

__global__ void __launch_bounds__(GRU_TPB, 1) __cluster_dims__(8, 1, 1)
gru_kernel(const float* __restrict__ h0,
           const float* __restrict__ w_hh,
           const float* __restrict__ b_hh,
           const float* __restrict__ w_out) {
    __shared__ __align__(16) unsigned long long htag[2][HDIM];
    __shared__ __align__(16) float h_s[HDIM];
    __shared__ float gh_s[96];

    int tid = threadIdx.x;
    int blk = blockIdx.x;

    // ---- worker clusters: w_out fp32 -> fp16 ----
    if (blk >= GRU_NBLK) {
        int base = (blk - GRU_NBLK) * GRU_TPB + tid;
        const int stride = WRK_NBLK * GRU_TPB;
        for (int idx = base; idx < VOCAB * 64; idx += stride) {
            int v  = idx >> 6;
            int k4 = (idx & 63) * 4;
            float4 w = *reinterpret_cast<const float4*>(
                &w_out[(size_t)v * HDIM + k4]);
            __half2 h01 = __floats2half2_rn(w.x, w.y);
            __half2 h23 = __floats2half2_rn(w.z, w.w);
            *reinterpret_cast<__half2*>(&g_B2[(size_t)v * HDIM + k4])     = h01;
            *reinterpret_cast<__half2*>(&g_B2[(size_t)v * HDIM + k4 + 2]) = h23;
        }
        return;
    }

    // ---- GRU clusters (blocks 0..63), protocol identical to verified R9 ----
    int b = blk >> 3;        // batch = cluster id
    int g = blk & 7;         // unit group = cluster rank

    int lr = tid >> 2;       // local gate row 0..95
    int ks = tid & 3;        // k-slice 0..3
    int gate = lr >> 5;
    int u    = lr & 31;
    int grow = gate * HDIM + g * 32 + u;
    int lane = tid & 31;

    unsigned long long w2[32];
#pragma unroll
    for (int j = 0; j < 16; j++) {
        float4 wv = *reinterpret_cast<const float4*>(
            &w_hh[(size_t)grow * HDIM + (j * 4 + ks) * 4]);
        w2[2 * j]     = f2_pack(wv.x, wv.y);
        w2[2 * j + 1] = f2_pack(wv.z, wv.w);
    }
    float bias = b_hh[grow];

    {
        unsigned long long* ft = &htag[0][0];
        for (int i = tid; i < 2 * HDIM; i += GRU_TPB) ft[i] = 0ull;
    }
    __syncthreads();
    CLUSTER_BAR();

    uint32_t poll_addr[2];
    {
        uint32_t a0 = smem_u32(&htag[0][tid < HDIM ? tid : 0]);
        uint32_t a1 = smem_u32(&htag[1][tid < HDIM ? tid : 0]);
        poll_addr[0] = mapa_u32(a0, (uint32_t)g);
        poll_addr[1] = mapa_u32(a1, (uint32_t)g);
    }
    uint32_t pub_addr[2][8];
    {
        uint32_t a0 = smem_u32(&htag[0][g * 32 + lane]);
        uint32_t a1 = smem_u32(&htag[1][g * 32 + lane]);
#pragma unroll
        for (int r = 0; r < 8; r++) {
            pub_addr[0][r] = mapa_u32(a0, (uint32_t)r);
            pub_addr[1][r] = mapa_u32(a1, (uint32_t)r);
        }
    }

    float hold = 0.f;
    if (tid < 32) {
        hold = h0[g * 32 + lane];
        unsigned long long word =
            (1ull << 32) | (unsigned long long)__float_as_uint(hold);
#pragma unroll
        for (int r = 0; r < 8; r++) st_clu64(pub_addr[0][r], word);
    }

    for (int s = 0; s < SEQ; s++) {
        int p = s & 1;
        unsigned want = (unsigned)(s + 1);

        float gir = 0.f, giz = 0.f, gin = 0.f;
        if (tid < 32) {
            size_t m = (size_t)b * SEQ + s;
            const float* gm = &g_gi[m * G3 + g * 32 + lane];
            gir = __ldg(gm);
            giz = __ldg(gm + HDIM);
            gin = __ldg(gm + 2 * HDIM);
        }

        if (tid < HDIM) {
            unsigned long long v = ld_clu64(poll_addr[p]);
            while ((unsigned)(v >> 32) != want) v = ld_clu64(poll_addr[p]);
            h_s[tid] = __uint_as_float((unsigned)v);
        }
        __syncthreads();

        unsigned long long acc0 = 0ull, acc1 = 0ull;
        const ulonglong2* hp = reinterpret_cast<const ulonglong2*>(h_s);
#pragma unroll
        for (int j = 0; j < 16; j++) {
            ulonglong2 hv = hp[j * 4 + ks];
            acc0 = f2_fma(w2[2 * j],     hv.x, acc0);
            acc1 = f2_fma(w2[2 * j + 1], hv.y, acc1);
        }
        float a0, a1, a2, a3;
        f2_unpack(acc0, a0, a1);
        f2_unpack(acc1, a2, a3);
        float acc = (a0 + a1) + (a2 + a3);
        acc += __shfl_xor_sync(0xffffffffu, acc, 1);
        acc += __shfl_xor_sync(0xffffffffu, acc, 2);
        if (ks == 0) gh_s[lr] = acc + bias;
        __syncthreads();

        if (tid < 32) {
            float hrv = gh_s[lane];
            float hzv = gh_s[32 + lane];
            float hnv = gh_s[64 + lane];
            float r = __fdividef(1.f, 1.f + __expf(-(gir + hrv)));
            float z = __fdividef(1.f, 1.f + __expf(-(giz + hzv)));
            float e2 = __expf(-2.f * (gin + r * hnv));
            float n = __fdividef(2.f, 1.f + e2) - 1.f;
            float hnew = (1.f - z) * n + z * hold;
            hold = hnew;
            if (s + 1 < SEQ) {
                unsigned long long word =
                    ((unsigned long long)(unsigned)(s + 2) << 32) |
                    (unsigned long long)__float_as_uint(hnew);
#pragma unroll
                for (int r8 = 0; r8 < 8; r8++)
                    st_clu64(pub_addr[p ^ 1][r8], word);
            }
            g_A2[((size_t)b * SEQ + s) * HDIM + g * 32 + lane] =
                __float2half_rn(hnew);
        }
    }
}

// =====================================================================
// Kernel C v3: out = A2 @ B2^T + b_out, mma.sync m16n8k16 fp16.
// CTA tile 256x128 (512 threads, 16 warps as 4x4) -> halves B re-reads
// (L2 traffic 1.5GB -> 1.28GB). Warp-level code identical to the
// verified R8/R13 tile; same K-chunk order => identical accumulation.
// =====================================================================
#define KCH      64
#define NCHUNKS  4
#define ROWB     144                      // (64+8) fp16 row stride in bytes
#define STG_ROWS 384                      // 256 A rows + 128 B rows
#define STG_SZ   (STG_ROWS * ROWB)        // 55296 B
#define SA(st)   ((st) * STG_SZ)
#define SB(st)   ((st) * STG_SZ + 256 * ROWB)
#define GEMM_SMEM (2 * STG_SZ)            // 110592 B

__global__ void __launch_bounds__(512, 1)
out_gemm_mma(const float* __restrict__ b_out, float* __restrict__ out) {
    extern __shared__ char smem[];
    uint32_t sb = smem_u32(smem);
    int tid = threadIdx.x;
    int wid = tid >> 5;           // 0..15
    int lane = tid & 31;
    int warp_m = wid >> 2;        // 0..3
    int warp_n = wid & 3;         // 0..3
    int m0 = blockIdx.y * 256;
    int n0 = blockIdx.x * 128;

    int g = lane >> 2;            // 0..7
    int t = lane & 3;             // 0..3

    // preload bias (off the epilogue critical path)
    float2 bi[4];
#pragma unroll
    for (int nt = 0; nt < 4; nt++)
        bi[nt] = *reinterpret_cast<const float2*>(
            &b_out[n0 + warp_n * 32 + nt * 8 + 2 * t]);

    auto issue = [&](int c, int buf) {
        // A: 256 rows x 64 cols fp16 = 2048 x 16B
#pragma unroll
        for (int i = 0; i < 4; i++) {
            int f = tid + 512 * i;       // 0..2047
            int row = f >> 3;            // 0..255
            int q = f & 7;
            cpa16(sb + SA(buf) + row * ROWB + q * 16,
                  &g_A2[(size_t)(m0 + row) * HDIM + c * KCH + q * 8]);
        }
        // B: 128 rows = 1024 x 16B
#pragma unroll
        for (int i = 0; i < 2; i++) {
            int f = tid + 512 * i;       // 0..1023
            int row = f >> 3;            // 0..127
            int q = f & 7;
            cpa16(sb + SB(buf) + row * ROWB + q * 16,
                  &g_B2[(size_t)(n0 + row) * HDIM + c * KCH + q * 8]);
        }
    };

    // verified lane formulas (R8); warp_m now spans 4 x 64 rows
    uint32_t a_lane = (uint32_t)((warp_m * 64 + (lane & 15)) * ROWB +
                                 ((lane >> 4) & 1) * 16);
    uint32_t b_lane = (uint32_t)((warp_n * 32 + (lane & 7) +
                                  ((lane >> 4) & 1) * 8) * ROWB +
                                 ((lane >> 3) & 1) * 16);

    float acc[4][4][4];
#pragma unroll
    for (int i = 0; i < 4; i++)
#pragma unroll
        for (int j = 0; j < 4; j++)
#pragma unroll
            for (int e = 0; e < 4; e++) acc[i][j][e] = 0.f;

    issue(0, 0);
    CPA_COMMIT();

    for (int c = 0; c < NCHUNKS; c++) {
        int buf = c & 1;
        CPA_WAIT0();
        __syncthreads();
        if (c + 1 < NCHUNKS) {
            issue(c + 1, buf ^ 1);
            CPA_COMMIT();
        }
        uint32_t abase = sb + SA(buf) + a_lane;
        uint32_t bbase = sb + SB(buf) + b_lane;
#pragma unroll
        for (int ks = 0; ks < 4; ks++) {
            uint32_t kb = (uint32_t)(ks * 32);   // 16 fp16 = 32 bytes
            uint32_t a[4][4];
#pragma unroll
            for (int mt = 0; mt < 4; mt++)
                ldsm4(abase + mt * 16 * ROWB + kb,
                      a[mt][0], a[mt][1], a[mt][2], a[mt][3]);
            uint32_t bq[4][2];
#pragma unroll
            for (int p = 0; p < 2; p++) {
                uint32_t r0, r1, r2, r3;
                ldsm4(bbase + p * 16 * ROWB + kb, r0, r1, r2, r3);
                bq[2 * p][0] = r0;     bq[2 * p][1] = r1;
                bq[2 * p + 1][0] = r2; bq[2 * p + 1][1] = r3;
            }
#pragma unroll
            for (int mt = 0; mt < 4; mt++)
#pragma unroll
                for (int nt = 0; nt < 4; nt++)
                    mma16816h(acc[mt][nt], a[mt][0], a[mt][1], a[mt][2],
                              a[mt][3], bq[nt][0], bq[nt][1]);
        }
        __syncthreads();
    }

#pragma unroll
    for (int mt = 0; mt < 4; mt++) {
        int r0 = m0 + warp_m * 64 + mt * 16 + g;
#pragma unroll
        for (int nt = 0; nt < 4; nt++) {
            int col = n0 + warp_n * 32 + nt * 8 + 2 * t;
            float2 o0 = {acc[mt][nt][0] + bi[nt].x, acc[mt][nt][1] + bi[nt].y};
            float2 o1 = {acc[mt][nt][2] + bi[nt].x, acc[mt][nt][3] + bi[nt].y};
            *reinterpret_cast<float2*>(&out[(size_t)r0 * VOCAB + col]) = o0;
            *reinterpret_cast<float2*>(&out[(size_t)(r0 + 8) * VOCAB + col]) = o1;
        }
    }
}

// =====================================================================
// launch
// =====================================================================
extern "C" void kernel_launch(void* const* d_in, const int* in_sizes, int n_in,
                              void* d_out, int out_size) {
    const int*   t     = (const int*)d_in[0];
    const float* emb   = (const float*)d_in[1];
    const float* h0    = (const float*)d_in[2];
    const float* w_ih  = (const float*)d_in[3];
    const float* w_hh  = (const float*)d_in[4];
    const float* b_ih  = (const float*)d_in[5];
    const float* b_hh  = (const float*)d_in[6];
    const float* w_out = (const float*)d_in[7];
    const float* b_out = (const float*)d_in[8];
    float* out = (float*)d_out;

    cudaFuncSetAttribute(embed_gi_kernel,
                         cudaFuncAttributeMaxDynamicSharedMemorySize,
                         EMB_SMEM);
    cudaFuncSetAttribute(out_gemm_mma,
                         cudaFuncAttributeMaxDynamicSharedMemorySize,
                         GEMM_SMEM);

    embed_gi_kernel<<<dim3(G3 / 128, MTOT / 128), 256, EMB_SMEM>>>(
        t, emb, w_ih, b_ih);
    gru_kernel<<<TOT_NBLK, GRU_TPB>>>(h0, w_hh, b_hh, w_out);
    out_gemm_mma<<<dim3(VOCAB / 128, MTOT / 256), 512, GEMM_SMEM>>>(b_out, out);
}

// round 16
// speedup vs baseline: 1.0651x; 1.0651x over previous
#include <cuda_runtime.h>
#include <cuda_bf16.h>
#include <cuda_fp16.h>
#include <cstdint>

#define VOCAB 32000
#define EDIM  128
#define HDIM  256
#define NBATCH 8
#define SEQ   512
#define MTOT  (NBATCH * SEQ)   // 4096
#define G3    (3 * HDIM)       // 768

// ---- scratch (static device globals; no allocation) ----
__device__ float g_gi[MTOT * G3];
__device__ __half g_A2[(size_t)MTOT * HDIM];    // [4096][256] fp16 hidden
__device__ __half g_B2[(size_t)VOCAB * HDIM];   // [32000][256] fp16 w_out

// ---- packed f32x2 helpers ----
__device__ __forceinline__ unsigned long long f2_pack(float x, float y) {
    unsigned long long r;
    asm("mov.b64 %0, {%1, %2};" : "=l"(r) : "f"(x), "f"(y));
    return r;
}
__device__ __forceinline__ unsigned long long f2_fma(unsigned long long a,
                                                     unsigned long long b,
                                                     unsigned long long c) {
    unsigned long long d;
    asm("fma.rn.f32x2 %0, %1, %2, %3;" : "=l"(d) : "l"(a), "l"(b), "l"(c));
    return d;
}
__device__ __forceinline__ unsigned long long f2_add(unsigned long long a,
                                                     unsigned long long b) {
    unsigned long long d;
    asm("add.rn.f32x2 %0, %1, %2;" : "=l"(d) : "l"(a), "l"(b));
    return d;
}
__device__ __forceinline__ void f2_unpack(unsigned long long v, float& lo, float& hi) {
    asm("mov.b64 {%0, %1}, %2;" : "=f"(lo), "=f"(hi) : "l"(v));
}
__device__ __forceinline__ uint32_t smem_u32(const void* p) {
    uint32_t a;
    asm("{ .reg .u64 t; cvta.to.shared.u64 t, %1; cvt.u32.u64 %0, t; }"
        : "=r"(a) : "l"(p));
    return a;
}

// ---- cluster / DSMEM helpers (sm_90 baseline PTX, no 'a' gating) ----
__device__ __forceinline__ uint32_t mapa_u32(uint32_t saddr, uint32_t rank) {
    uint32_t r;
    asm("mapa.shared::cluster.u32 %0, %1, %2;" : "=r"(r) : "r"(saddr), "r"(rank));
    return r;
}
__device__ __forceinline__ void st_clu64(uint32_t addr, unsigned long long v) {
    asm volatile("st.relaxed.cluster.shared::cluster.b64 [%0], %1;"
                 :: "r"(addr), "l"(v) : "memory");
}
__device__ __forceinline__ unsigned long long ld_clu64(uint32_t addr) {
    unsigned long long v;
    asm volatile("ld.relaxed.cluster.shared::cluster.b64 %0, [%1];"
                 : "=l"(v) : "r"(addr) : "memory");
    return v;
}
#define CLUSTER_BAR() do {                                          \
    asm volatile("barrier.cluster.arrive.aligned;" ::: "memory");   \
    asm volatile("barrier.cluster.wait.aligned;" ::: "memory");     \
} while (0)

// ---- mma.sync / ldmatrix / cp.async helpers (sm_80+ PTX, target-safe) ----
__device__ __forceinline__ void ldsm4(uint32_t addr, uint32_t& r0, uint32_t& r1,
                                      uint32_t& r2, uint32_t& r3) {
    asm volatile("ldmatrix.sync.aligned.m8n8.x4.shared.b16 {%0,%1,%2,%3}, [%4];"
                 : "=r"(r0), "=r"(r1), "=r"(r2), "=r"(r3) : "r"(addr));
}
__device__ __forceinline__ void mma16816h(float* c, uint32_t a0, uint32_t a1,
                                          uint32_t a2, uint32_t a3,
                                          uint32_t b0, uint32_t b1) {
    asm volatile(
        "mma.sync.aligned.m16n8k16.row.col.f32.f16.f16.f32 "
        "{%0,%1,%2,%3}, {%4,%5,%6,%7}, {%8,%9}, {%0,%1,%2,%3};"
        : "+f"(c[0]), "+f"(c[1]), "+f"(c[2]), "+f"(c[3])
        : "r"(a0), "r"(a1), "r"(a2), "r"(a3), "r"(b0), "r"(b1));
}
__device__ __forceinline__ void cpa16(uint32_t s, const void* g) {
    asm volatile("cp.async.cg.shared.global [%0], [%1], 16;" :: "r"(s), "l"(g));
}
#define CPA_COMMIT() asm volatile("cp.async.commit_group;" ::: "memory")
#define CPA_WAIT0()  asm volatile("cp.async.wait_group 0;" ::: "memory")

// =====================================================================
// Kernel A v2: gi = emb[t] @ w_ih^T + b_ih  (verified R14 version).
// =====================================================================
#define E_ASTRIDE 260
#define E_BSTRIDE 132
#define E_NCH     8
#define EMB_SMEM  ((2 * 16 * E_ASTRIDE + 2 * 16 * E_BSTRIDE) * (int)sizeof(float))

__global__ void __launch_bounds__(256, 2)
embed_gi_kernel(const int* __restrict__ t,
                const float* __restrict__ emb,
                const float* __restrict__ w_ih,
                const float* __restrict__ b_ih) {
    extern __shared__ float esm[];
    float* As2 = esm;
    float* Bsm = esm + 2 * 16 * E_ASTRIDE;
    __shared__ int tok[128];

    int tid = threadIdx.x;
    int n0 = blockIdx.x * 128;
    int m0 = blockIdx.y * 128;

    if (tid < 128) tok[tid] = t[m0 + tid];
    __syncthreads();

    int lrow = tid >> 2;
    int lc4  = (tid & 3) * 4;

    const float* a0p = &emb[(size_t)tok[lrow] * EDIM + lc4];
    const float* a1p = &emb[(size_t)tok[lrow + 64] * EDIM + lc4];
    const float* b0p = &w_ih[(size_t)(n0 + lrow) * EDIM + lc4];
    const float* b1p = b0p + (size_t)64 * EDIM;

    auto stage = [&](int nb, float4 xa0, float4 xa1, float4 xb0, float4 xb1) {
        float* ab = &As2[nb * 16 * E_ASTRIDE];
        float* bb = &Bsm[nb * 16 * E_BSTRIDE];
        float av0[4] = {xa0.x, xa0.y, xa0.z, xa0.w};
        float av1[4] = {xa1.x, xa1.y, xa1.z, xa1.w};
        float bv0[4] = {xb0.x, xb0.y, xb0.z, xb0.w};
        float bv1[4] = {xb1.x, xb1.y, xb1.z, xb1.w};
#pragma unroll
        for (int c = 0; c < 4; c++) {
            *reinterpret_cast<unsigned long long*>(
                &ab[(lc4 + c) * E_ASTRIDE + 2 * lrow]) = f2_pack(av0[c], av0[c]);
            *reinterpret_cast<unsigned long long*>(
                &ab[(lc4 + c) * E_ASTRIDE + 2 * (lrow + 64)]) =
                f2_pack(av1[c], av1[c]);
            bb[(lc4 + c) * E_BSTRIDE + lrow]      = bv0[c];
            bb[(lc4 + c) * E_BSTRIDE + lrow + 64] = bv1[c];
        }
    };

    {
        float4 xa0 = *reinterpret_cast<const float4*>(a0p);
        float4 xa1 = *reinterpret_cast<const float4*>(a1p);
        float4 xb0 = *reinterpret_cast<const float4*>(b0p);
        float4 xb1 = *reinterpret_cast<const float4*>(b1p);
        stage(0, xa0, xa1, xb0, xb1);
    }
    __syncthreads();

    int tm = tid >> 4;
    int tn = tid & 15;

    unsigned long long c2[8][4];
#pragma unroll
    for (int i = 0; i < 8; i++)
#pragma unroll
        for (int j = 0; j < 4; j++) c2[i][j] = 0ull;

    for (int ksg = 0; ksg < E_NCH; ksg++) {
        int buf = ksg & 1;
        float4 na0, na1, nb0, nb1;
        if (ksg < E_NCH - 1) {
            int off = (ksg + 1) * 16;
            na0 = *reinterpret_cast<const float4*>(a0p + off);
            na1 = *reinterpret_cast<const float4*>(a1p + off);
            nb0 = *reinterpret_cast<const float4*>(b0p + off);
            nb1 = *reinterpret_cast<const float4*>(b1p + off);
        }
#pragma unroll
        for (int kk = 0; kk < 16; kk++) {
            const unsigned long long* arow =
                reinterpret_cast<const unsigned long long*>(
                    &As2[(buf * 16 + kk) * E_ASTRIDE]) + tm * 8;
            const float* brow = &Bsm[(buf * 16 + kk) * E_BSTRIDE + tn * 8];
            ulonglong2 bq0 = *reinterpret_cast<const ulonglong2*>(brow);
            ulonglong2 bq1 = *reinterpret_cast<const ulonglong2*>(brow + 4);
#pragma unroll
            for (int i = 0; i < 8; i++) {
                unsigned long long ap = arow[i];
                c2[i][0] = f2_fma(ap, bq0.x, c2[i][0]);
                c2[i][1] = f2_fma(ap, bq0.y, c2[i][1]);
                c2[i][2] = f2_fma(ap, bq1.x, c2[i][2]);
                c2[i][3] = f2_fma(ap, bq1.y, c2[i][3]);
            }
        }
        if (ksg < E_NCH - 1) {
            __syncthreads();
            stage(buf ^ 1, na0, na1, nb0, nb1);
            __syncthreads();
        }
    }

    float4 bb0 = *reinterpret_cast<const float4*>(&b_ih[n0 + tn * 8]);
    float4 bb1 = *reinterpret_cast<const float4*>(&b_ih[n0 + tn * 8 + 4]);
    unsigned long long bo[4] = {f2_pack(bb0.x, bb0.y), f2_pack(bb0.z, bb0.w),
                                f2_pack(bb1.x, bb1.y), f2_pack(bb1.z, bb1.w)};
#pragma unroll
    for (int i = 0; i < 8; i++) {
        union { unsigned long long u[4]; float4 f[2]; } r;
        r.u[0] = f2_add(c2[i][0], bo[0]);
        r.u[1] = f2_add(c2[i][1], bo[1]);
        r.u[2] = f2_add(c2[i][2], bo[2]);
        r.u[3] = f2_add(c2[i][3], bo[3]);
        float* orow = &g_gi[(size_t)(m0 + tm * 8 + i) * G3 + n0 + tn * 8];
        *reinterpret_cast<float4*>(orow)     = r.f[0];
        *reinterpret_cast<float4*>(orow + 4) = r.f[1];
    }
}

// =====================================================================
// Kernel B: GRU recurrence with DSMEM tag exchange (verified R9-R14)
// PLUS worker clusters (w_out -> fp16). Fast-math combine (R14).
// =====================================================================
#define GRU_NBLK 64
#define GRU_TPB  384
#define WRK_NBLK 56
#define TOT_NBLK (GRU_NBLK + WRK_NBLK)   // 120, divisible by 8

__global__ void __launch_bounds__(GRU_TPB, 1) __cluster_dims__(8, 1, 1)
gru_kernel(const float* __restrict__ h0,
           const float* __restrict__ w_hh,
           const float* __restrict__ b_hh,
           const float* __restrict__ w_out) {
    __shared__ __align__(16) unsigned long long htag[2][HDIM];
    __shared__ __align__(16) float h_s[HDIM];
    __shared__ float gh_s[96];

    int tid = threadIdx.x;
    int blk = blockIdx.x;

    // ---- worker clusters: w_out fp32 -> fp16 ----
    if (blk >= GRU_NBLK) {
        int base = (blk - GRU_NBLK) * GRU_TPB + tid;
        const int stride = WRK_NBLK * GRU_TPB;
        for (int idx = base; idx < VOCAB * 64; idx += stride) {
            int v  = idx >> 6;
            int k4 = (idx & 63) * 4;
            float4 w = *reinterpret_cast<const float4*>(
                &w_out[(size_t)v * HDIM + k4]);
            __half2 h01 = __floats2half2_rn(w.x, w.y);
            __half2 h23 = __floats2half2_rn(w.z, w.w);
            *reinterpret_cast<__half2*>(&g_B2[(size_t)v * HDIM + k4])     = h01;
            *reinterpret_cast<__half2*>(&g_B2[(size_t)v * HDIM + k4 + 2]) = h23;
        }
        return;
    }

    // ---- GRU clusters (blocks 0..63), protocol identical to verified R9 ----
    int b = blk >> 3;        // batch = cluster id
    int g = blk & 7;         // unit group = cluster rank

    int lr = tid >> 2;       // local gate row 0..95
    int ks = tid & 3;        // k-slice 0..3
    int gate = lr >> 5;
    int u    = lr & 31;
    int grow = gate * HDIM + g * 32 + u;
    int lane = tid & 31;

    unsigned long long w2[32];
#pragma unroll
    for (int j = 0; j < 16; j++) {
        float4 wv = *reinterpret_cast<const float4*>(
            &w_hh[(size_t)grow * HDIM + (j * 4 + ks) * 4]);
        w2[2 * j]     = f2_pack(wv.x, wv.y);
        w2[2 * j + 1] = f2_pack(wv.z, wv.w);
    }
    float bias = b_hh[grow];

    {
        unsigned long long* ft = &htag[0][0];
        for (int i = tid; i < 2 * HDIM; i += GRU_TPB) ft[i] = 0ull;
    }
    __syncthreads();
    CLUSTER_BAR();

    uint32_t poll_addr[2];
    {
        uint32_t a0 = smem_u32(&htag[0][tid < HDIM ? tid : 0]);
        uint32_t a1 = smem_u32(&htag[1][tid < HDIM ? tid : 0]);
        poll_addr[0] = mapa_u32(a0, (uint32_t)g);
        poll_addr[1] = mapa_u32(a1, (uint32_t)g);
    }
    uint32_t pub_addr[2][8];
    {
        uint32_t a0 = smem_u32(&htag[0][g * 32 + lane]);
        uint32_t a1 = smem_u32(&htag[1][g * 32 + lane]);
#pragma unroll
        for (int r = 0; r < 8; r++) {
            pub_addr[0][r] = mapa_u32(a0, (uint32_t)r);
            pub_addr[1][r] = mapa_u32(a1, (uint32_t)r);
        }
    }

    float hold = 0.f;
    if (tid < 32) {
        hold = h0[g * 32 + lane];
        unsigned long long word =
            (1ull << 32) | (unsigned long long)__float_as_uint(hold);
#pragma unroll
        for (int r = 0; r < 8; r++) st_clu64(pub_addr[0][r], word);
    }

    for (int s = 0; s < SEQ; s++) {
        int p = s & 1;
        unsigned want = (unsigned)(s + 1);

        float gir = 0.f, giz = 0.f, gin = 0.f;
        if (tid < 32) {
            size_t m = (size_t)b * SEQ + s;
            const float* gm = &g_gi[m * G3 + g * 32 + lane];
            gir = __ldg(gm);
            giz = __ldg(gm + HDIM);
            gin = __ldg(gm + 2 * HDIM);
        }

        if (tid < HDIM) {
            unsigned long long v = ld_clu64(poll_addr[p]);
            while ((unsigned)(v >> 32) != want) v = ld_clu64(poll_addr[p]);
            h_s[tid] = __uint_as_float((unsigned)v);
        }
        __syncthreads();

        unsigned long long acc0 = 0ull, acc1 = 0ull;
        const ulonglong2* hp = reinterpret_cast<const ulonglong2*>(h_s);
#pragma unroll
        for (int j = 0; j < 16; j++) {
            ulonglong2 hv = hp[j * 4 + ks];
            acc0 = f2_fma(w2[2 * j],     hv.x, acc0);
            acc1 = f2_fma(w2[2 * j + 1], hv.y, acc1);
        }
        float a0, a1, a2, a3;
        f2_unpack(acc0, a0, a1);
        f2_unpack(acc1, a2, a3);
        float acc = (a0 + a1) + (a2 + a3);
        acc += __shfl_xor_sync(0xffffffffu, acc, 1);
        acc += __shfl_xor_sync(0xffffffffu, acc, 2);
        if (ks == 0) gh_s[lr] = acc + bias;
        __syncthreads();

        if (tid < 32) {
            float hrv = gh_s[lane];
            float hzv = gh_s[32 + lane];
            float hnv = gh_s[64 + lane];
            float r = __fdividef(1.f, 1.f + __expf(-(gir + hrv)));
            float z = __fdividef(1.f, 1.f + __expf(-(giz + hzv)));
            float e2 = __expf(-2.f * (gin + r * hnv));
            float n = __fdividef(2.f, 1.f + e2) - 1.f;
            float hnew = (1.f - z) * n + z * hold;
            hold = hnew;
            if (s + 1 < SEQ) {
                unsigned long long word =
                    ((unsigned long long)(unsigned)(s + 2) << 32) |
                    (unsigned long long)__float_as_uint(hnew);
#pragma unroll
                for (int r8 = 0; r8 < 8; r8++)
                    st_clu64(pub_addr[p ^ 1][r8], word);
            }
            g_A2[((size_t)b * SEQ + s) * HDIM + g * 32 + lane] =
                __float2half_rn(hnew);
        }
    }
}

// =====================================================================
// Kernel C v4: out = A2 @ B2^T + b_out, mma.sync m16n8k16 fp16.
// R14-verified 8-warp 128x128 warp structure, 256 threads, 2 CTAs/SM.
// Each CTA processes TWO m-subtiles against ONE resident full-K B tile
// (B loaded once: halves B L2 traffic, total 1.55GB -> 1.29GB).
// Same K-chunk order per output element -> identical accumulation.
// =====================================================================
#define KCH      64
#define NCHUNKS  4
#define ROWB     144                      // A chunk row stride (64+8 fp16)
#define ROWB2    528                      // B full-K row stride (256+8 fp16)
#define ABUF_SZ  (128 * ROWB)             // 18432 B
#define SBOFF    (2 * ABUF_SZ)            // B tile at 36864
#define GEMM_SMEM (2 * ABUF_SZ + 128 * ROWB2)   // 36864 + 67584 = 104448 B

__global__ void __launch_bounds__(256, 2)
out_gemm_mma(const float* __restrict__ b_out, float* __restrict__ out) {
    extern __shared__ char smem[];
    uint32_t sb = smem_u32(smem);
    int tid = threadIdx.x;
    int wid = tid >> 5;
    int lane = tid & 31;
    int warp_m = wid >> 2;        // 0..1
    int warp_n = wid & 3;         // 0..3
    int mbase = blockIdx.y * 256;
    int n0 = blockIdx.x * 128;

    int g = lane >> 2;            // 0..7
    int t = lane & 3;             // 0..3

    // preload bias (off the epilogue critical path)
    float2 bi[4];
#pragma unroll
    for (int nt = 0; nt < 4; nt++)
        bi[nt] = *reinterpret_cast<const float2*>(
            &b_out[n0 + warp_n * 32 + nt * 8 + 2 * t]);

    // load full-K B tile once: 128 rows x 256 fp16 = 4096 x 16B
    auto issueB = [&]() {
#pragma unroll
        for (int i = 0; i < 16; i++) {
            int f = tid + 256 * i;       // 0..4095
            int row = f >> 5;            // 0..127
            int q = f & 31;              // 0..31 (16B units)
            cpa16(sb + SBOFF + row * ROWB2 + q * 16,
                  &g_B2[(size_t)(n0 + row) * HDIM + q * 8]);
        }
    };
    // load one A chunk (msub, k-chunk c) into buffer buf
    auto issueA = [&](int msub, int c, int buf) {
        int m0 = mbase + msub * 128;
#pragma unroll
        for (int i = 0; i < 4; i++) {
            int f = tid + 256 * i;       // 0..1023
            int row = f >> 3;            // 0..127
            int q = f & 7;               // 0..7 (16B units)
            cpa16(sb + buf * ABUF_SZ + row * ROWB + q * 16,
                  &g_A2[(size_t)(m0 + row) * HDIM + c * KCH + q * 8]);
        }
    };

    // verified lane formulas (R8/R14)
    uint32_t a_lane = (uint32_t)((warp_m * 64 + (lane & 15)) * ROWB +
                                 ((lane >> 4) & 1) * 16);
    uint32_t b_lane = (uint32_t)((warp_n * 32 + (lane & 7) +
                                  ((lane >> 4) & 1) * 8) * ROWB2 +
                                 ((lane >> 3) & 1) * 16);

    issueB();
    CPA_COMMIT();
    issueA(0, 0, 0);
    CPA_COMMIT();

    for (int msub = 0; msub < 2; msub++) {
        float acc[4][4][4];
#pragma unroll
        for (int i = 0; i < 4; i++)
#pragma unroll
            for (int j = 0; j < 4; j++)
#pragma unroll
                for (int e = 0; e < 4; e++) acc[i][j][e] = 0.f;

        for (int c = 0; c < NCHUNKS; c++) {
            int buf = (msub * NCHUNKS + c) & 1;
            CPA_WAIT0();
            __syncthreads();
            if (c + 1 < NCHUNKS) {
                issueA(msub, c + 1, buf ^ 1);
                CPA_COMMIT();
            } else if (msub == 0) {
                issueA(1, 0, buf ^ 1);
                CPA_COMMIT();
            }
            uint32_t abase = sb + buf * ABUF_SZ + a_lane;
            uint32_t bbase = sb + SBOFF + b_lane + (uint32_t)(c * 128);
#pragma unroll
            for (int ks = 0; ks < 4; ks++) {
                uint32_t kb = (uint32_t)(ks * 32);   // 16 fp16 = 32 bytes
                uint32_t a[4][4];
#pragma unroll
                for (int mt = 0; mt < 4; mt++)
                    ldsm4(abase + mt * 16 * ROWB + kb,
                          a[mt][0], a[mt][1], a[mt][2], a[mt][3]);
                uint32_t bq[4][2];
#pragma unroll
                for (int p = 0; p < 2; p++) {
                    uint32_t r0, r1, r2, r3;
                    ldsm4(bbase + p * 16 * ROWB2 + kb, r0, r1, r2, r3);
                    bq[2 * p][0] = r0;     bq[2 * p][1] = r1;
                    bq[2 * p + 1][0] = r2; bq[2 * p + 1][1] = r3;
                }
#pragma unroll
                for (int mt = 0; mt < 4; mt++)
#pragma unroll
                    for (int nt = 0; nt < 4; nt++)
                        mma16816h(acc[mt][nt], a[mt][0], a[mt][1], a[mt][2],
                                  a[mt][3], bq[nt][0], bq[nt][1]);
            }
            __syncthreads();
        }

        int m0 = mbase + msub * 128;
#pragma unroll
        for (int mt = 0; mt < 4; mt++) {
            int r0 = m0 + warp_m * 64 + mt * 16 + g;
#pragma unroll
            for (int nt = 0; nt < 4; nt++) {
                int col = n0 + warp_n * 32 + nt * 8 + 2 * t;
                float2 o0 = {acc[mt][nt][0] + bi[nt].x,
                             acc[mt][nt][1] + bi[nt].y};
                float2 o1 = {acc[mt][nt][2] + bi[nt].x,
                             acc[mt][nt][3] + bi[nt].y};
                *reinterpret_cast<float2*>(&out[(size_t)r0 * VOCAB + col]) = o0;
                *reinterpret_cast<float2*>(
                    &out[(size_t)(r0 + 8) * VOCAB + col]) = o1;
            }
        }
    }
}

// =====================================================================
// launch
// =====================================================================
extern "C" void kernel_launch(void* const* d_in, const int* in_sizes, int n_in,
                              void* d_out, int out_size) {
    const int*   t     = (const int*)d_in[0];
    const float* emb   = (const float*)d_in[1];
    const float* h0    = (const float*)d_in[2];
    const float* w_ih  = (const float*)d_in[3];
    const float* w_hh  = (const float*)d_in[4];
    const float* b_ih  = (const float*)d_in[5];
    const float* b_hh  = (const float*)d_in[6];
    const float* w_out = (const float*)d_in[7];
    const float* b_out = (const float*)d_in[8];
    float* out = (float*)d_out;

    cudaFuncSetAttribute(embed_gi_kernel,
                         cudaFuncAttributeMaxDynamicSharedMemorySize,
                         EMB_SMEM);
    cudaFuncSetAttribute(out_gemm_mma,
                         cudaFuncAttributeMaxDynamicSharedMemorySize,
                         GEMM_SMEM);

    embed_gi_kernel<<<dim3(G3 / 128, MTOT / 128), 256, EMB_SMEM>>>(
        t, emb, w_ih, b_ih);
    gru_kernel<<<TOT_NBLK, GRU_TPB>>>(h0, w_hh, b_hh, w_out);
    out_gemm_mma<<<dim3(VOCAB / 128, MTOT / 256), 256, GEMM_SMEM>>>(b_out, out);
}

// round 17
// speedup vs baseline: 1.1593x; 1.0885x over previous
#include <cuda_runtime.h>
#include <cuda_bf16.h>
#include <cuda_fp16.h>
#include <cstdint>

#define VOCAB 32000
#define EDIM  128
#define HDIM  256
#define NBATCH 8
#define SEQ   512
#define MTOT  (NBATCH * SEQ)   // 4096
#define G3    (3 * HDIM)       // 768

// ---- scratch (static device globals; no allocation) ----
__device__ float g_gi[MTOT * G3];
__device__ __half g_A2[(size_t)MTOT * HDIM];    // [4096][256] fp16 hidden
__device__ __half g_B2[(size_t)VOCAB * HDIM];   // [32000][256] fp16 w_out
__device__ int g_prog[NBATCH * 8];              // GRU progress per (batch, rank)
__device__ int g_wdone;                         // worker blocks finished

// ---- packed f32x2 helpers ----
__device__ __forceinline__ unsigned long long f2_pack(float x, float y) {
    unsigned long long r;
    asm("mov.b64 %0, {%1, %2};" : "=l"(r) : "f"(x), "f"(y));
    return r;
}
__device__ __forceinline__ unsigned long long f2_fma(unsigned long long a,
                                                     unsigned long long b,
                                                     unsigned long long c) {
    unsigned long long d;
    asm("fma.rn.f32x2 %0, %1, %2, %3;" : "=l"(d) : "l"(a), "l"(b), "l"(c));
    return d;
}
__device__ __forceinline__ unsigned long long f2_add(unsigned long long a,
                                                     unsigned long long b) {
    unsigned long long d;
    asm("add.rn.f32x2 %0, %1, %2;" : "=l"(d) : "l"(a), "l"(b));
    return d;
}
__device__ __forceinline__ void f2_unpack(unsigned long long v, float& lo, float& hi) {
    asm("mov.b64 {%0, %1}, %2;" : "=f"(lo), "=f"(hi) : "l"(v));
}
__device__ __forceinline__ uint32_t smem_u32(const void* p) {
    uint32_t a;
    asm("{ .reg .u64 t; cvta.to.shared.u64 t, %1; cvt.u32.u64 %0, t; }"
        : "=r"(a) : "l"(p));
    return a;
}

// ---- acquire/release + sleep + PDL ----
__device__ __forceinline__ int ld_acq(const int* p) {
    int v;
    asm volatile("ld.acquire.gpu.global.b32 %0, [%1];" : "=r"(v) : "l"(p) : "memory");
    return v;
}
__device__ __forceinline__ void st_rel(int* p, int v) {
    asm volatile("st.release.gpu.global.b32 [%0], %1;" :: "l"(p), "r"(v) : "memory");
}
__device__ __forceinline__ void red_rel_add1(int* p) {
    asm volatile("red.release.gpu.global.add.u32 [%0], 1;" :: "l"(p) : "memory");
}
__device__ __forceinline__ void nsleep(unsigned n) {
    asm volatile("nanosleep.u32 %0;" :: "r"(n));
}
#define PDL_TRIGGER() asm volatile("griddepcontrol.launch_dependents;" ::: "memory")

// ---- cluster / DSMEM helpers (sm_90 baseline PTX, no 'a' gating) ----
__device__ __forceinline__ uint32_t mapa_u32(uint32_t saddr, uint32_t rank) {
    uint32_t r;
    asm("mapa.shared::cluster.u32 %0, %1, %2;" : "=r"(r) : "r"(saddr), "r"(rank));
    return r;
}
__device__ __forceinline__ void st_clu64(uint32_t addr, unsigned long long v) {
    asm volatile("st.relaxed.cluster.shared::cluster.b64 [%0], %1;"
                 :: "r"(addr), "l"(v) : "memory");
}
__device__ __forceinline__ unsigned long long ld_clu64(uint32_t addr) {
    unsigned long long v;
    asm volatile("ld.relaxed.cluster.shared::cluster.b64 %0, [%1];"
                 : "=l"(v) : "r"(addr) : "memory");
    return v;
}
#define CLUSTER_BAR() do {                                          \
    asm volatile("barrier.cluster.arrive.aligned;" ::: "memory");   \
    asm volatile("barrier.cluster.wait.aligned;" ::: "memory");     \
} while (0)

// ---- mma.sync / ldmatrix / cp.async helpers (sm_80+ PTX, target-safe) ----
__device__ __forceinline__ void ldsm4(uint32_t addr, uint32_t& r0, uint32_t& r1,
                                      uint32_t& r2, uint32_t& r3) {
    asm volatile("ldmatrix.sync.aligned.m8n8.x4.shared.b16 {%0,%1,%2,%3}, [%4];"
                 : "=r"(r0), "=r"(r1), "=r"(r2), "=r"(r3) : "r"(addr));
}
__device__ __forceinline__ void mma16816h(float* c, uint32_t a0, uint32_t a1,
                                          uint32_t a2, uint32_t a3,
                                          uint32_t b0, uint32_t b1) {
    asm volatile(
        "mma.sync.aligned.m16n8k16.row.col.f32.f16.f16.f32 "
        "{%0,%1,%2,%3}, {%4,%5,%6,%7}, {%8,%9}, {%0,%1,%2,%3};"
        : "+f"(c[0]), "+f"(c[1]), "+f"(c[2]), "+f"(c[3])
        : "r"(a0), "r"(a1), "r"(a2), "r"(a3), "r"(b0), "r"(b1));
}
__device__ __forceinline__ void cpa16(uint32_t s, const void* g) {
    asm volatile("cp.async.cg.shared.global [%0], [%1], 16;" :: "r"(s), "l"(g));
}
#define CPA_COMMIT() asm volatile("cp.async.commit_group;" ::: "memory")
#define CPA_WAIT0()  asm volatile("cp.async.wait_group 0;" ::: "memory")

// =====================================================================
// Kernel A v2: gi = emb[t] @ w_ih^T + b_ih (verified R14). Block (0,0)
// also resets the overlap counters (stream-ordered before GRU/GEMM).
// =====================================================================
#define E_ASTRIDE 260
#define E_BSTRIDE 132
#define E_NCH     8
#define EMB_SMEM  ((2 * 16 * E_ASTRIDE + 2 * 16 * E_BSTRIDE) * (int)sizeof(float))

__global__ void __launch_bounds__(256, 2)
embed_gi_kernel(const int* __restrict__ t,
                const float* __restrict__ emb,
                const float* __restrict__ w_ih,
                const float* __restrict__ b_ih) {
    extern __shared__ float esm[];
    float* As2 = esm;
    float* Bsm = esm + 2 * 16 * E_ASTRIDE;
    __shared__ int tok[128];

    int tid = threadIdx.x;
    if (blockIdx.x == 0 && blockIdx.y == 0) {
        if (tid < NBATCH * 8) g_prog[tid] = 0;
        if (tid == 64) g_wdone = 0;
    }
    int n0 = blockIdx.x * 128;
    int m0 = blockIdx.y * 128;

    if (tid < 128) tok[tid] = t[m0 + tid];
    __syncthreads();

    int lrow = tid >> 2;
    int lc4  = (tid & 3) * 4;

    const float* a0p = &emb[(size_t)tok[lrow] * EDIM + lc4];
    const float* a1p = &emb[(size_t)tok[lrow + 64] * EDIM + lc4];
    const float* b0p = &w_ih[(size_t)(n0 + lrow) * EDIM + lc4];
    const float* b1p = b0p + (size_t)64 * EDIM;

    auto stage = [&](int nb, float4 xa0, float4 xa1, float4 xb0, float4 xb1) {
        float* ab = &As2[nb * 16 * E_ASTRIDE];
        float* bb = &Bsm[nb * 16 * E_BSTRIDE];
        float av0[4] = {xa0.x, xa0.y, xa0.z, xa0.w};
        float av1[4] = {xa1.x, xa1.y, xa1.z, xa1.w};
        float bv0[4] = {xb0.x, xb0.y, xb0.z, xb0.w};
        float bv1[4] = {xb1.x, xb1.y, xb1.z, xb1.w};
#pragma unroll
        for (int c = 0; c < 4; c++) {
            *reinterpret_cast<unsigned long long*>(
                &ab[(lc4 + c) * E_ASTRIDE + 2 * lrow]) = f2_pack(av0[c], av0[c]);
            *reinterpret_cast<unsigned long long*>(
                &ab[(lc4 + c) * E_ASTRIDE + 2 * (lrow + 64)]) =
                f2_pack(av1[c], av1[c]);
            bb[(lc4 + c) * E_BSTRIDE + lrow]      = bv0[c];
            bb[(lc4 + c) * E_BSTRIDE + lrow + 64] = bv1[c];
        }
    };

    {
        float4 xa0 = *reinterpret_cast<const float4*>(a0p);
        float4 xa1 = *reinterpret_cast<const float4*>(a1p);
        float4 xb0 = *reinterpret_cast<const float4*>(b0p);
        float4 xb1 = *reinterpret_cast<const float4*>(b1p);
        stage(0, xa0, xa1, xb0, xb1);
    }
    __syncthreads();

    int tm = tid >> 4;
    int tn = tid & 15;

    unsigned long long c2[8][4];
#pragma unroll
    for (int i = 0; i < 8; i++)
#pragma unroll
        for (int j = 0; j < 4; j++) c2[i][j] = 0ull;

    for (int ksg = 0; ksg < E_NCH; ksg++) {
        int buf = ksg & 1;
        float4 na0, na1, nb0, nb1;
        if (ksg < E_NCH - 1) {
            int off = (ksg + 1) * 16;
            na0 = *reinterpret_cast<const float4*>(a0p + off);
            na1 = *reinterpret_cast<const float4*>(a1p + off);
            nb0 = *reinterpret_cast<const float4*>(b0p + off);
            nb1 = *reinterpret_cast<const float4*>(b1p + off);
        }
#pragma unroll
        for (int kk = 0; kk < 16; kk++) {
            const unsigned long long* arow =
                reinterpret_cast<const unsigned long long*>(
                    &As2[(buf * 16 + kk) * E_ASTRIDE]) + tm * 8;
            const float* brow = &Bsm[(buf * 16 + kk) * E_BSTRIDE + tn * 8];
            ulonglong2 bq0 = *reinterpret_cast<const ulonglong2*>(brow);
            ulonglong2 bq1 = *reinterpret_cast<const ulonglong2*>(brow + 4);
#pragma unroll
            for (int i = 0; i < 8; i++) {
                unsigned long long ap = arow[i];
                c2[i][0] = f2_fma(ap, bq0.x, c2[i][0]);
                c2[i][1] = f2_fma(ap, bq0.y, c2[i][1]);
                c2[i][2] = f2_fma(ap, bq1.x, c2[i][2]);
                c2[i][3] = f2_fma(ap, bq1.y, c2[i][3]);
            }
        }
        if (ksg < E_NCH - 1) {
            __syncthreads();
            stage(buf ^ 1, na0, na1, nb0, nb1);
            __syncthreads();
        }
    }

    float4 bb0 = *reinterpret_cast<const float4*>(&b_ih[n0 + tn * 8]);
    float4 bb1 = *reinterpret_cast<const float4*>(&b_ih[n0 + tn * 8 + 4]);
    unsigned long long bo[4] = {f2_pack(bb0.x, bb0.y), f2_pack(bb0.z, bb0.w),
                                f2_pack(bb1.x, bb1.y), f2_pack(bb1.z, bb1.w)};
#pragma unroll
    for (int i = 0; i < 8; i++) {
        union { unsigned long long u[4]; float4 f[2]; } r;
        r.u[0] = f2_add(c2[i][0], bo[0]);
        r.u[1] = f2_add(c2[i][1], bo[1]);
        r.u[2] = f2_add(c2[i][2], bo[2]);
        r.u[3] = f2_add(c2[i][3], bo[3]);
        float* orow = &g_gi[(size_t)(m0 + tm * 8 + i) * G3 + n0 + tn * 8];
        *reinterpret_cast<float4*>(orow)     = r.f[0];
        *reinterpret_cast<float4*>(orow + 4) = r.f[1];
    }
}

// =====================================================================
// Kernel B: GRU recurrence with DSMEM tag exchange (verified R9-R16)
// + worker clusters (w_out -> fp16, release-counted)
// + PDL trigger + progress releases at s=256/512 for the gated GEMM.
// =====================================================================
#define GRU_NBLK 64
#define GRU_TPB  384
#define WRK_NBLK 56
#define TOT_NBLK (GRU_NBLK + WRK_NBLK)   // 120, divisible by 8

__global__ void __launch_bounds__(GRU_TPB, 1) __cluster_dims__(8, 1, 1)
gru_kernel(const float* __restrict__ h0,
           const float* __restrict__ w_hh,
           const float* __restrict__ b_hh,
           const float* __restrict__ w_out) {
    __shared__ __align__(16) unsigned long long htag[2][HDIM];
    __shared__ __align__(16) float h_s[HDIM];
    __shared__ float gh_s[96];

    int tid = threadIdx.x;
    int blk = blockIdx.x;

    PDL_TRIGGER();   // let the gated GEMM grid start scheduling on idle SMs

    // ---- worker clusters: w_out fp32 -> fp16 ----
    if (blk >= GRU_NBLK) {
        int base = (blk - GRU_NBLK) * GRU_TPB + tid;
        const int stride = WRK_NBLK * GRU_TPB;
        for (int idx = base; idx < VOCAB * 64; idx += stride) {
            int v  = idx >> 6;
            int k4 = (idx & 63) * 4;
            float4 w = *reinterpret_cast<const float4*>(
                &w_out[(size_t)v * HDIM + k4]);
            __half2 h01 = __floats2half2_rn(w.x, w.y);
            __half2 h23 = __floats2half2_rn(w.z, w.w);
            *reinterpret_cast<__half2*>(&g_B2[(size_t)v * HDIM + k4])     = h01;
            *reinterpret_cast<__half2*>(&g_B2[(size_t)v * HDIM + k4 + 2]) = h23;
        }
        __syncthreads();                 // block-wide fence: stores visible
        if (tid == 0) red_rel_add1(&g_wdone);
        return;
    }

    // ---- GRU clusters (blocks 0..63), protocol identical to verified R9 ----
    int b = blk >> 3;        // batch = cluster id
    int g = blk & 7;         // unit group = cluster rank

    int lr = tid >> 2;       // local gate row 0..95
    int ks = tid & 3;        // k-slice 0..3
    int gate = lr >> 5;
    int u    = lr & 31;
    int grow = gate * HDIM + g * 32 + u;
    int lane = tid & 31;

    unsigned long long w2[32];
#pragma unroll
    for (int j = 0; j < 16; j++) {
        float4 wv = *reinterpret_cast<const float4*>(
            &w_hh[(size_t)grow * HDIM + (j * 4 + ks) * 4]);
        w2[2 * j]     = f2_pack(wv.x, wv.y);
        w2[2 * j + 1] = f2_pack(wv.z, wv.w);
    }
    float bias = b_hh[grow];

    {
        unsigned long long* ft = &htag[0][0];
        for (int i = tid; i < 2 * HDIM; i += GRU_TPB) ft[i] = 0ull;
    }
    __syncthreads();
    CLUSTER_BAR();

    uint32_t poll_addr[2];
    {
        uint32_t a0 = smem_u32(&htag[0][tid < HDIM ? tid : 0]);
        uint32_t a1 = smem_u32(&htag[1][tid < HDIM ? tid : 0]);
        poll_addr[0] = mapa_u32(a0, (uint32_t)g);
        poll_addr[1] = mapa_u32(a1, (uint32_t)g);
    }
    uint32_t pub_addr[2][8];
    {
        uint32_t a0 = smem_u32(&htag[0][g * 32 + lane]);
        uint32_t a1 = smem_u32(&htag[1][g * 32 + lane]);
#pragma unroll
        for (int r = 0; r < 8; r++) {
            pub_addr[0][r] = mapa_u32(a0, (uint32_t)r);
            pub_addr[1][r] = mapa_u32(a1, (uint32_t)r);
        }
    }

    float hold = 0.f;
    if (tid < 32) {
        hold = h0[g * 32 + lane];
        unsigned long long word =
            (1ull << 32) | (unsigned long long)__float_as_uint(hold);
#pragma unroll
        for (int r = 0; r < 8; r++) st_clu64(pub_addr[0][r], word);
    }

    for (int s = 0; s < SEQ; s++) {
        int p = s & 1;
        unsigned want = (unsigned)(s + 1);

        float gir = 0.f, giz = 0.f, gin = 0.f;
        if (tid < 32) {
            size_t m = (size_t)b * SEQ + s;
            const float* gm = &g_gi[m * G3 + g * 32 + lane];
            gir = __ldg(gm);
            giz = __ldg(gm + HDIM);
            gin = __ldg(gm + 2 * HDIM);
        }

        if (tid < HDIM) {
            unsigned long long v = ld_clu64(poll_addr[p]);
            while ((unsigned)(v >> 32) != want) v = ld_clu64(poll_addr[p]);
            h_s[tid] = __uint_as_float((unsigned)v);
        }
        __syncthreads();

        unsigned long long acc0 = 0ull, acc1 = 0ull;
        const ulonglong2* hp = reinterpret_cast<const ulonglong2*>(h_s);
#pragma unroll
        for (int j = 0; j < 16; j++) {
            ulonglong2 hv = hp[j * 4 + ks];
            acc0 = f2_fma(w2[2 * j],     hv.x, acc0);
            acc1 = f2_fma(w2[2 * j + 1], hv.y, acc1);
        }
        float a0, a1, a2, a3;
        f2_unpack(acc0, a0, a1);
        f2_unpack(acc1, a2, a3);
        float acc = (a0 + a1) + (a2 + a3);
        acc += __shfl_xor_sync(0xffffffffu, acc, 1);
        acc += __shfl_xor_sync(0xffffffffu, acc, 2);
        if (ks == 0) gh_s[lr] = acc + bias;
        __syncthreads();

        if (tid < 32) {
            float hrv = gh_s[lane];
            float hzv = gh_s[32 + lane];
            float hnv = gh_s[64 + lane];
            float r = __fdividef(1.f, 1.f + __expf(-(gir + hrv)));
            float z = __fdividef(1.f, 1.f + __expf(-(giz + hzv)));
            float e2 = __expf(-2.f * (gin + r * hnv));
            float n = __fdividef(2.f, 1.f + e2) - 1.f;
            float hnew = (1.f - z) * n + z * hold;
            hold = hnew;
            if (s + 1 < SEQ) {
                unsigned long long word =
                    ((unsigned long long)(unsigned)(s + 2) << 32) |
                    (unsigned long long)__float_as_uint(hnew);
#pragma unroll
                for (int r8 = 0; r8 < 8; r8++)
                    st_clu64(pub_addr[p ^ 1][r8], word);
            }
            g_A2[((size_t)b * SEQ + s) * HDIM + g * 32 + lane] =
                __float2half_rn(hnew);
            // progress release at the two gate thresholds (A2 visible first:
            // __syncwarp carries memory-ordering among the warp's lanes)
            if (s == 255 || s == 511) {
                __syncwarp(0xffffffffu);
                if (lane == 0) st_rel(&g_prog[b * 8 + g], s + 1);
            }
        }
    }
}

// =====================================================================
// Kernel C v4 + gate: out = A2 @ B2^T + b_out (verified R16 GEMM body).
// blockIdx.y -> (batch, sblk); tile waits (sleep-poll, acquire) until
// its A2 rows and B2 are published. If PDL overlap is unavailable the
// gates are already open and behavior is identical to R16.
// =====================================================================
#define KCH      64
#define NCHUNKS  4
#define ROWB     144                      // A chunk row stride (64+8 fp16)
#define ROWB2    528                      // B full-K row stride (256+8 fp16)
#define ABUF_SZ  (128 * ROWB)             // 18432 B
#define SBOFF    (2 * ABUF_SZ)            // B tile at 36864
#define GEMM_SMEM (2 * ABUF_SZ + 128 * ROWB2)   // 104448 B

__global__ void __launch_bounds__(256, 2)
out_gemm_mma(const float* __restrict__ b_out, float* __restrict__ out) {
    extern __shared__ char smem[];
    uint32_t sb = smem_u32(smem);
    int tid = threadIdx.x;
    int wid = tid >> 5;
    int lane = tid & 31;
    int warp_m = wid >> 2;        // 0..1
    int warp_n = wid & 3;         // 0..3
    int b8   = blockIdx.y & 7;    // batch
    int sblk = blockIdx.y >> 3;   // 0 = steps 0..255, 1 = steps 256..511
    int mbase = b8 * SEQ + sblk * 256;
    int n0 = blockIdx.x * 128;

    // gate: B2 fully converted AND this (batch, sblk) A2 range published
    if (tid == 0) {
        while (ld_acq(&g_wdone) < WRK_NBLK) nsleep(1024);
        int need = (sblk + 1) * 256;
#pragma unroll
        for (int g8 = 0; g8 < 8; g8++)
            while (ld_acq(&g_prog[b8 * 8 + g8]) < need) nsleep(1024);
    }
    __syncthreads();

    int g = lane >> 2;            // 0..7
    int t = lane & 3;             // 0..3

    float2 bi[4];
#pragma unroll
    for (int nt = 0; nt < 4; nt++)
        bi[nt] = *reinterpret_cast<const float2*>(
            &b_out[n0 + warp_n * 32 + nt * 8 + 2 * t]);

    auto issueB = [&]() {
#pragma unroll
        for (int i = 0; i < 16; i++) {
            int f = tid + 256 * i;       // 0..4095
            int row = f >> 5;
            int q = f & 31;
            cpa16(sb + SBOFF + row * ROWB2 + q * 16,
                  &g_B2[(size_t)(n0 + row) * HDIM + q * 8]);
        }
    };
    auto issueA = [&](int msub, int c, int buf) {
        int m0 = mbase + msub * 128;
#pragma unroll
        for (int i = 0; i < 4; i++) {
            int f = tid + 256 * i;
            int row = f >> 3;
            int q = f & 7;
            cpa16(sb + buf * ABUF_SZ + row * ROWB + q * 16,
                  &g_A2[(size_t)(m0 + row) * HDIM + c * KCH + q * 8]);
        }
    };

    uint32_t a_lane = (uint32_t)((warp_m * 64 + (lane & 15)) * ROWB +
                                 ((lane >> 4) & 1) * 16);
    uint32_t b_lane = (uint32_t)((warp_n * 32 + (lane & 7) +
                                  ((lane >> 4) & 1) * 8) * ROWB2 +
                                 ((lane >> 3) & 1) * 16);

    issueB();
    CPA_COMMIT();
    issueA(0, 0, 0);
    CPA_COMMIT();

    for (int msub = 0; msub < 2; msub++) {
        float acc[4][4][4];
#pragma unroll
        for (int i = 0; i < 4; i++)
#pragma unroll
            for (int j = 0; j < 4; j++)
#pragma unroll
                for (int e = 0; e < 4; e++) acc[i][j][e] = 0.f;

        for (int c = 0; c < NCHUNKS; c++) {
            int buf = (msub * NCHUNKS + c) & 1;
            CPA_WAIT0();
            __syncthreads();
            if (c + 1 < NCHUNKS) {
                issueA(msub, c + 1, buf ^ 1);
                CPA_COMMIT();
            } else if (msub == 0) {
                issueA(1, 0, buf ^ 1);
                CPA_COMMIT();
            }
            uint32_t abase = sb + buf * ABUF_SZ + a_lane;
            uint32_t bbase = sb + SBOFF + b_lane + (uint32_t)(c * 128);
#pragma unroll
            for (int ks = 0; ks < 4; ks++) {
                uint32_t kb = (uint32_t)(ks * 32);
                uint32_t a[4][4];
#pragma unroll
                for (int mt = 0; mt < 4; mt++)
                    ldsm4(abase + mt * 16 * ROWB + kb,
                          a[mt][0], a[mt][1], a[mt][2], a[mt][3]);
                uint32_t bq[4][2];
#pragma unroll
                for (int p = 0; p < 2; p++) {
                    uint32_t r0, r1, r2, r3;
                    ldsm4(bbase + p * 16 * ROWB2 + kb, r0, r1, r2, r3);
                    bq[2 * p][0] = r0;     bq[2 * p][1] = r1;
                    bq[2 * p + 1][0] = r2; bq[2 * p + 1][1] = r3;
                }
#pragma unroll
                for (int mt = 0; mt < 4; mt++)
#pragma unroll
                    for (int nt = 0; nt < 4; nt++)
                        mma16816h(acc[mt][nt], a[mt][0], a[mt][1], a[mt][2],
                                  a[mt][3], bq[nt][0], bq[nt][1]);
            }
            __syncthreads();
        }

        int m0 = mbase + msub * 128;
#pragma unroll
        for (int mt = 0; mt < 4; mt++) {
            int r0 = m0 + warp_m * 64 + mt * 16 + g;
#pragma unroll
            for (int nt = 0; nt < 4; nt++) {
                int col = n0 + warp_n * 32 + nt * 8 + 2 * t;
                float2 o0 = {acc[mt][nt][0] + bi[nt].x,
                             acc[mt][nt][1] + bi[nt].y};
                float2 o1 = {acc[mt][nt][2] + bi[nt].x,
                             acc[mt][nt][3] + bi[nt].y};
                *reinterpret_cast<float2*>(&out[(size_t)r0 * VOCAB + col]) = o0;
                *reinterpret_cast<float2*>(
                    &out[(size_t)(r0 + 8) * VOCAB + col]) = o1;
            }
        }
    }
}

// =====================================================================
// launch
// =====================================================================
extern "C" void kernel_launch(void* const* d_in, const int* in_sizes, int n_in,
                              void* d_out, int out_size) {
    const int*   t     = (const int*)d_in[0];
    const float* emb   = (const float*)d_in[1];
    const float* h0    = (const float*)d_in[2];
    const float* w_ih  = (const float*)d_in[3];
    const float* w_hh  = (const float*)d_in[4];
    const float* b_ih  = (const float*)d_in[5];
    const float* b_hh  = (const float*)d_in[6];
    const float* w_out = (const float*)d_in[7];
    const float* b_out = (const float*)d_in[8];
    float* out = (float*)d_out;

    cudaFuncSetAttribute(embed_gi_kernel,
                         cudaFuncAttributeMaxDynamicSharedMemorySize,
                         EMB_SMEM);
    cudaFuncSetAttribute(out_gemm_mma,
                         cudaFuncAttributeMaxDynamicSharedMemorySize,
                         GEMM_SMEM);

    embed_gi_kernel<<<dim3(G3 / 128, MTOT / 128), 256, EMB_SMEM>>>(
        t, emb, w_ih, b_ih);
    gru_kernel<<<TOT_NBLK, GRU_TPB>>>(h0, w_hh, b_hh, w_out);

    // GEMM with programmatic dependent launch: overlaps the GRU tail,
    // correctness guaranteed by the acquire gates inside the kernel.
    cudaLaunchConfig_t cfg = {};
    cfg.gridDim = dim3(VOCAB / 128, MTOT / 256);
    cfg.blockDim = dim3(256);
    cfg.dynamicSmemBytes = GEMM_SMEM;
    cfg.stream = 0;
    cudaLaunchAttribute at[1];
    at[0].id = cudaLaunchAttributeProgrammaticStreamSerialization;
    at[0].val.programmaticStreamSerializationAllowed = 1;
    cfg.attrs = at;
    cfg.numAttrs = 1;
    cudaLaunchKernelEx(&cfg, out_gemm_mma, b_out, out);
}